// round 3
// baseline (speedup 1.0000x reference)
#include <cuda_runtime.h>
#include <math.h>

#define SEQL 512
#define BATCH 64
#define INF 512
#define HID 1024
#define OUTF 512
#define NBLK 128
#define SCAN_THREADS 512

typedef unsigned long long u64;

// Scratch (device globals; allocation-free)
// g_xi: starts as xi = x@i_h + b_i; the scan accumulates h_{t-1}@W into it,
//       so after the scan g_xi[t] = raw_t (pre-activation). h_t = tanh(raw_t).
__device__ float g_xi[(size_t)SEQL * BATCH * HID];   // [t][b][c] row-major
__device__ float g_h [(size_t)SEQL * BATCH * HID];   // tanh(raw), row-major
__device__ unsigned g_count = 0;
__device__ unsigned g_phase = 0;

// ---------------- f32x2 helpers ----------------
__device__ __forceinline__ u64 pack2(float x, float y) {
    u64 d; asm("mov.b64 %0,{%1,%2};" : "=l"(d) : "f"(x), "f"(y)); return d;
}
__device__ __forceinline__ float2 unpack2(u64 d) {
    float2 v; asm("mov.b64 {%0,%1},%2;" : "=f"(v.x), "=f"(v.y) : "l"(d)); return v;
}
__device__ __forceinline__ u64 fma2(u64 a, u64 b, u64 c) {
    u64 d; asm("fma.rn.f32x2 %0,%1,%2,%3;" : "=l"(d) : "l"(a), "l"(b), "l"(c)); return d;
}

// ---------------------------------------------------------------------------
// Persistent scan. 128 blocks = 16 colgroups x 8 ksplits.
// Block (cg, kq): owns W[kbeg:kbeg+128, cb:cb+64] in SMEM (dup f32x2, 64KB).
// Per step t:
//   stage: hS[k][r] = tanh(raw[t-1][r][kbeg+k])  (t=0: h0, no tanh) -- 32KB,
//          XOR-swizzled rows for conflict-free STS/LDS.
//   GEMM : 64 rows x 64 cols x 128 k, f32x2, pure SMEM operands.
//   write: atomicAdd partials into xi[t] (L2 reduction across the 8 ksplits).
//   grid barrier (phase flip), 1 per step.
// ---------------------------------------------------------------------------
__global__ void __launch_bounds__(SCAN_THREADS, 1) rnn_scan(
    const float* __restrict__ h0, const float* __restrict__ W,
    float* __restrict__ xi)
{
    extern __shared__ char smdyn[];
    u64*   wS2 = (u64*)smdyn;                 // [128 k][64 c] dup pairs = 64KB
    float* hS  = (float*)(smdyn + 65536);     // [128 k][64 r] swizzled = 32KB

    const int tid = threadIdx.x;
    const int cg  = blockIdx.x >> 3;          // colgroup 0..15
    const int kq_ = blockIdx.x & 7;           // ksplit  0..7
    const int cb  = cg * 64;
    const int kbeg = kq_ * 128;

    // Load W slice once (dup'd pairs)
    for (int i = tid; i < 128 * 64; i += SCAN_THREADS) {
        int k = i >> 6, c = i & 63;
        float w = W[(size_t)(kbeg + k) * HID + cb + c];
        wS2[i] = pack2(w, w);
    }

    // thread mapping for GEMM: warps = qg(2) x cg_w(8); lanes = cp(4) x qd(8)
    const int wid = tid >> 5, lane = tid & 31;
    const int qg   = wid & 1;                 // row half of rowquads
    const int cg_w = wid >> 1;                // col group within block
    const int qd = lane & 7, cp = lane >> 3;
    const int rq    = qg * 8 + qd;            // rowquad 0..15 -> rows 4rq..4rq+3
    const int cpair = cg_w * 4 + cp;          // 0..31 -> cols 2cpair, 2cpair+1

    // staging mapping
    const int sr  = tid >> 3;                 // row 0..63
    const int skq = tid & 7;                  // k chunk-of-16: 0..7
    const int srr = sr ^ (skq << 2);          // swizzled row

    for (int t = 0; t < SEQL; ++t) {
        // ---- stage tanh(h_{t-1}) slice into SMEM ----
        {
            const float* src = (t == 0)
                ? h0 + (size_t)sr * HID + kbeg + skq * 16
                : xi + (size_t)(t - 1) * BATCH * HID + (size_t)sr * HID + kbeg + skq * 16;
            __syncthreads();  // protect hS reuse from previous step's readers
#pragma unroll
            for (int j4 = 0; j4 < 4; ++j4) {
                float4 v = *(const float4*)(src + j4 * 4);
                if (t != 0) {
                    v.x = tanhf(v.x); v.y = tanhf(v.y);
                    v.z = tanhf(v.z); v.w = tanhf(v.w);
                }
                int k = skq * 16 + j4 * 4;
                hS[(k + 0) * 64 + srr] = v.x;
                hS[(k + 1) * 64 + srr] = v.y;
                hS[(k + 2) * 64 + srr] = v.z;
                hS[(k + 3) * 64 + srr] = v.w;
            }
        }
        __syncthreads();

        // ---- 64x64x128 f32x2 GEMM from SMEM ----
        u64 a00 = 0, a01 = 0, a10 = 0, a11 = 0;
#pragma unroll
        for (int kq = 0; kq < 8; ++kq) {
            const float* hb = hS  + kq * 16 * 64 + 4 * (rq ^ kq);
            const u64*   wb = wS2 + kq * 16 * 64 + 2 * cpair;
#pragma unroll
            for (int kk = 0; kk < 16; ++kk) {
                ulonglong2 hv = *(const ulonglong2*)(hb + kk * 64);
                ulonglong2 wv = *(const ulonglong2*)(wb + kk * 64);
                a00 = fma2(hv.x, wv.x, a00);
                a10 = fma2(hv.y, wv.x, a10);
                a01 = fma2(hv.x, wv.y, a01);
                a11 = fma2(hv.y, wv.y, a11);
            }
        }

        // ---- atomic reduce into xi[t] ----
        {
            float* dst = xi + (size_t)t * BATCH * HID;
            const int r0 = 4 * rq;
            const int c0 = cb + 2 * cpair;
            float2 f;
            f = unpack2(a00);
            atomicAdd(&dst[(size_t)(r0 + 0) * HID + c0],     f.x);
            atomicAdd(&dst[(size_t)(r0 + 1) * HID + c0],     f.y);
            f = unpack2(a01);
            atomicAdd(&dst[(size_t)(r0 + 0) * HID + c0 + 1], f.x);
            atomicAdd(&dst[(size_t)(r0 + 1) * HID + c0 + 1], f.y);
            f = unpack2(a10);
            atomicAdd(&dst[(size_t)(r0 + 2) * HID + c0],     f.x);
            atomicAdd(&dst[(size_t)(r0 + 3) * HID + c0],     f.y);
            f = unpack2(a11);
            atomicAdd(&dst[(size_t)(r0 + 2) * HID + c0 + 1], f.x);
            atomicAdd(&dst[(size_t)(r0 + 3) * HID + c0 + 1], f.y);
        }

        // ---- grid barrier ----
        __threadfence();   // make this thread's atomics globally visible
        __syncthreads();
        if (tid == 0) {
            unsigned ph;
            asm volatile("ld.acquire.gpu.u32 %0,[%1];" : "=r"(ph) : "l"(&g_phase) : "memory");
            unsigned arrived = atomicAdd(&g_count, 1u);
            if (arrived == NBLK - 1) {
                g_count = 0;
                __threadfence();
                atomicExch(&g_phase, ph + 1);
            } else {
                unsigned cur;
                do {
                    __nanosleep(20);
                    asm volatile("ld.acquire.gpu.u32 %0,[%1];" : "=r"(cur) : "l"(&g_phase) : "memory");
                } while (cur == ph);
                __threadfence();
            }
        }
        __syncthreads();
    }
}

// ---------------------------------------------------------------------------
// 128x128x8 f32x2 GEMM: C = A @ B + bias, optional leaky-relu. Row-major A.
// ---------------------------------------------------------------------------
template <bool LEAKY>
__global__ __launch_bounds__(256) void sgemm_f2(
    const float* __restrict__ A, const float* __restrict__ B,
    const float* __restrict__ bias, float* __restrict__ C,
    int M, int N, int K)
{
    constexpr int BM = 128, BN = 128, BK = 8;
    __shared__ __align__(16) float As[BK][BM];
    __shared__ __align__(16) float Bs[BK][BN];

    const int tid = threadIdx.x;
    const int bx = blockIdx.x, by = blockIdx.y;
    const int tx = tid & 15, ty = tid >> 4;

    u64 acc[8][4];
#pragma unroll
    for (int i = 0; i < 8; i++)
#pragma unroll
        for (int j = 0; j < 4; j++) acc[i][j] = 0ull;

    const int aRow = tid >> 1, aCol = (tid & 1) * 4;
    const int bRow = tid >> 5, bCol = (tid & 31) * 4;

    for (int k0 = 0; k0 < K; k0 += BK) {
        float4 av = *(const float4*)(A + (size_t)(by * BM + aRow) * K + k0 + aCol);
        As[aCol + 0][aRow] = av.x;
        As[aCol + 1][aRow] = av.y;
        As[aCol + 2][aRow] = av.z;
        As[aCol + 3][aRow] = av.w;
        *(float4*)&Bs[bRow][bCol] =
            *(const float4*)(B + (size_t)(k0 + bRow) * N + bx * BN + bCol);
        __syncthreads();

#pragma unroll
        for (int kk = 0; kk < BK; kk++) {
            float4 alo = *(const float4*)&As[kk][ty * 8];
            float4 ahi = *(const float4*)&As[kk][ty * 8 + 4];
            ulonglong2 b01 = *(const ulonglong2*)&Bs[kk][tx * 8];
            ulonglong2 b23 = *(const ulonglong2*)&Bs[kk][tx * 8 + 4];
            float a[8] = {alo.x, alo.y, alo.z, alo.w, ahi.x, ahi.y, ahi.z, ahi.w};
#pragma unroll
            for (int i = 0; i < 8; i++) {
                u64 ad = pack2(a[i], a[i]);
                acc[i][0] = fma2(ad, b01.x, acc[i][0]);
                acc[i][1] = fma2(ad, b01.y, acc[i][1]);
                acc[i][2] = fma2(ad, b23.x, acc[i][2]);
                acc[i][3] = fma2(ad, b23.y, acc[i][3]);
            }
        }
        __syncthreads();
    }

    const int row0 = by * BM + ty * 8, col0 = bx * BN + tx * 8;
#pragma unroll
    for (int i = 0; i < 8; i++) {
        float out[8];
#pragma unroll
        for (int j = 0; j < 4; j++) {
            float2 f = unpack2(acc[i][j]);
            out[2 * j] = f.x; out[2 * j + 1] = f.y;
        }
#pragma unroll
        for (int j = 0; j < 8; j++) {
            float v = out[j] + bias[col0 + j];
            if (LEAKY) v = v >= 0.f ? v : 0.01f * v;
            out[j] = v;
        }
        *(float4*)&C[(size_t)(row0 + i) * N + col0]     = make_float4(out[0], out[1], out[2], out[3]);
        *(float4*)&C[(size_t)(row0 + i) * N + col0 + 4] = make_float4(out[4], out[5], out[6], out[7]);
    }
}

// ---------------------------------------------------------------------------
__global__ void tanh_pass(const float* __restrict__ raw, float* __restrict__ h, size_t n4) {
    size_t i = (size_t)blockIdx.x * blockDim.x + threadIdx.x;
    if (i < n4) {
        float4 v = ((const float4*)raw)[i];
        v.x = tanhf(v.x); v.y = tanhf(v.y); v.z = tanhf(v.z); v.w = tanhf(v.w);
        ((float4*)h)[i] = v;
    }
}

__global__ void hfinal_pass(const float* __restrict__ rawlast, float* __restrict__ out) {
    int i = blockIdx.x * 256 + threadIdx.x;   // 65536
    out[i] = tanhf(rawlast[i]);
}

// ---------------------------------------------------------------------------
extern "C" void kernel_launch(void* const* d_in, const int* in_sizes, int n_in,
                              void* d_out, int out_size)
{
    const float* x   = (const float*)d_in[0];
    const float* h0  = (const float*)d_in[1];
    const float* i_h = (const float*)d_in[2];
    const float* h_h = (const float*)d_in[3];
    const float* h_o = (const float*)d_in[4];
    const float* b_i = (const float*)d_in[5];
    const float* b_o = (const float*)d_in[6];
    float* out = (float*)d_out;

    float *xi = nullptr, *h = nullptr;
    cudaGetSymbolAddress((void**)&xi, g_xi);
    cudaGetSymbolAddress((void**)&h,  g_h);

    static int smem_set = 0;
    if (!smem_set) {
        cudaFuncSetAttribute(rnn_scan, cudaFuncAttributeMaxDynamicSharedMemorySize, 98304);
        smem_set = 1;
    }

    // 1) xi = x @ i_h + b_i : [32768,512]@[512,1024]
    {
        dim3 grid(HID / 128, (SEQL * BATCH) / 128);
        sgemm_f2<false><<<grid, 256>>>(x, i_h, b_i, xi, SEQL * BATCH, HID, INF);
    }

    // 2) persistent scan: xi[t] += h_{t-1} @ h_h  (raw preactivations)
    rnn_scan<<<NBLK, SCAN_THREADS, 98304>>>(h0, h_h, xi);

    // 3) h = tanh(raw)
    {
        size_t n4 = (size_t)SEQL * BATCH * HID / 4;
        tanh_pass<<<(unsigned)((n4 + 255) / 256), 256>>>(xi, h, n4);
    }

    // 4) outputs = leaky_relu(h @ h_o + b_o) : [32768,1024]@[1024,512]
    {
        dim3 grid(OUTF / 128, (SEQL * BATCH) / 128);
        sgemm_f2<true><<<grid, 256>>>(h, h_o, b_o, out, SEQL * BATCH, OUTF, HID);
    }

    // 5) h_final = tanh(raw[511])
    hfinal_pass<<<256, 256>>>(xi + (size_t)(SEQL - 1) * BATCH * HID,
                              out + (size_t)SEQL * BATCH * OUTF);
}

// round 4
// speedup vs baseline: 1.1362x; 1.1362x over previous
#include <cuda_runtime.h>
#include <math.h>

#define SEQL 512
#define BATCH 64
#define INF 512
#define HID 1024
#define OUTF 512
#define NBLK 128
#define SCAN_THREADS 512

typedef unsigned long long u64;

// Scratch (device globals; allocation-free)
__device__ float g_xi [(size_t)SEQL * BATCH * HID];   // [t][b][c] row-major
__device__ float g_hsT[(size_t)SEQL * BATCH * HID];   // [t][c][r] transposed
__device__ float g_h0T[(size_t)BATCH * HID];          // [c][r]
__device__ unsigned g_count = 0;
__device__ unsigned g_phase = 0;

// ---------------- f32x2 helpers ----------------
__device__ __forceinline__ u64 pack2(float x, float y) {
    u64 d; asm("mov.b64 %0,{%1,%2};" : "=l"(d) : "f"(x), "f"(y)); return d;
}
__device__ __forceinline__ float2 unpack2(u64 d) {
    float2 v; asm("mov.b64 {%0,%1},%2;" : "=f"(v.x), "=f"(v.y) : "l"(d)); return v;
}
__device__ __forceinline__ u64 fma2(u64 a, u64 b, u64 c) {
    u64 d; asm("fma.rn.f32x2 %0,%1,%2,%3;" : "=l"(d) : "l"(a), "l"(b), "l"(c)); return d;
}
__device__ __forceinline__ u64 add2(u64 a, u64 b) {
    u64 d; asm("add.rn.f32x2 %0,%1,%2;" : "=l"(d) : "l"(a), "l"(b)); return d;
}

// ---------------------------------------------------------------------------
// Persistent scan: h_t = tanh(xi_t + h_{t-1} @ W). 128 blocks x 512 threads.
// Block b owns output cols [8b, 8b+8); W slice (1024x8) in SMEM as dup pairs.
// Warps: 8 k-splits x 2 row-halves; lane tile 4 rows x 2 cols (4 FMA2/k).
// xi values for the reduction are prefetched at step start (hide DRAM lat).
// ---------------------------------------------------------------------------
__global__ void __launch_bounds__(SCAN_THREADS, 1) rnn_scan(
    const float* __restrict__ h0T, const float* __restrict__ W,
    const float* __restrict__ xi, float* __restrict__ hsT)
{
    extern __shared__ u64 smdyn[];
    u64* wS2  = smdyn;           // [1024][8] dup pairs = 64KB
    u64* sRed = smdyn + 8192;    // [8 ksplit][8 col][32 rowpair] = 16KB

    const int tid = threadIdx.x;
    const int cb  = blockIdx.x * 8;

    for (int i = tid; i < 8192; i += SCAN_THREADS) {
        int k = i >> 3, c = i & 7;
        float w = W[(size_t)k * HID + cb + c];
        wS2[i] = pack2(w, w);
    }
    __syncthreads();

    const int wg   = tid >> 5, l = tid & 31;
    const int q    = wg >> 1;          // k-split 0..7
    const int half = wg & 1;           // row half
    const int qd   = l & 7;
    const int cg   = l >> 3;           // col pair 0..3
    const int rowoff = half * 32 + qd * 4;
    const int kbeg = q * 128;

    const int rp2 = tid & 31;          // reduction role (tid<256)
    const int rc  = tid >> 5;          // local col 0..7

    for (int t = 0; t < SEQL; ++t) {
        // ---- prefetch xi for this step's reduction (DRAM, hidden by GEMM) --
        float x0 = 0.f, x1 = 0.f;
        if (tid < 256) {
            const float* xit = xi + (size_t)t * BATCH * HID;
            x0 = __ldg(&xit[(size_t)(2 * rp2)     * HID + cb + rc]);
            x1 = __ldg(&xit[(size_t)(2 * rp2 + 1) * HID + cb + rc]);
        }

        const float* hin = t ? hsT + (size_t)(t - 1) * BATCH * HID : h0T;
        u64 a0 = 0, a1 = 0, a2 = 0, a3 = 0;
        const float* hp = hin + (size_t)kbeg * 64 + rowoff;
        const u64*   wp = wS2 + (size_t)kbeg * 8 + 2 * cg;
#pragma unroll 8
        for (int k = 0; k < 128; ++k) {
            ulonglong2 hv = *(const ulonglong2*)(hp + (size_t)k * 64);
            ulonglong2 wv = *(const ulonglong2*)(wp + (size_t)k * 8);
            a0 = fma2(hv.x, wv.x, a0);
            a1 = fma2(hv.y, wv.x, a1);
            a2 = fma2(hv.x, wv.y, a2);
            a3 = fma2(hv.y, wv.y, a3);
        }
        {
            int rp = half * 16 + qd * 2;
            sRed[((size_t)q * 8 + 2 * cg)     * 32 + rp    ] = a0;
            sRed[((size_t)q * 8 + 2 * cg)     * 32 + rp + 1] = a1;
            sRed[((size_t)q * 8 + 2 * cg + 1) * 32 + rp    ] = a2;
            sRed[((size_t)q * 8 + 2 * cg + 1) * 32 + rp + 1] = a3;
        }
        __syncthreads();

        if (tid < 256) {
            u64 s = sRed[(size_t)rc * 32 + rp2];
#pragma unroll
            for (int qq = 1; qq < 8; ++qq)
                s = add2(s, sRed[((size_t)qq * 8 + rc) * 32 + rp2]);
            float2 f = unpack2(s);
            float v0 = tanhf(f.x + x0);
            float v1 = tanhf(f.y + x1);
            *(u64*)(hsT + (size_t)t * BATCH * HID + (size_t)(cb + rc) * 64 + 2 * rp2)
                = pack2(v0, v1);
        }
        __syncthreads();

        // ---- grid barrier (spin, no sleep) ----
        if (tid == 0) {
            __threadfence();
            unsigned ph;
            asm volatile("ld.acquire.gpu.u32 %0,[%1];" : "=r"(ph) : "l"(&g_phase) : "memory");
            unsigned arrived = atomicAdd(&g_count, 1u);
            if (arrived == NBLK - 1) {
                g_count = 0;
                __threadfence();
                atomicExch(&g_phase, ph + 1);
            } else {
                unsigned cur;
                do {
                    asm volatile("ld.acquire.gpu.u32 %0,[%1];" : "=r"(cur) : "l"(&g_phase) : "memory");
                } while (cur == ph);
            }
        }
        __syncthreads();
    }
}

// ---------------------------------------------------------------------------
// Double-buffered 128x128x16 f32x2 GEMM: C = A @ B + bias, optional leaky.
// Register-prefetch pipeline, one __syncthreads per K-tile.
// ATRANS: A stored as [M/64][K][64] (transposed hidden-state history).
// ---------------------------------------------------------------------------
template <bool ATRANS, bool LEAKY>
__global__ __launch_bounds__(256) void sgemm_db(
    const float* __restrict__ A, const float* __restrict__ B,
    const float* __restrict__ bias, float* __restrict__ C,
    int M, int N, int K)
{
    constexpr int BM = 128, BN = 128, BK = 16;
    __shared__ __align__(16) float As[2][BK][BM];
    __shared__ __align__(16) float Bs[2][BK][BN];

    const int tid = threadIdx.x;
    const int bx = blockIdx.x, by = blockIdx.y;
    const int tx = tid & 15, ty = tid >> 4;

    u64 acc[8][4];
#pragma unroll
    for (int i = 0; i < 8; i++)
#pragma unroll
        for (int j = 0; j < 4; j++) acc[i][j] = 0ull;

    // A mapping (row-major): row = tid>>1, col8 = (tid&1)*8
    const int aRow = tid >> 1, aC = (tid & 1) * 8;
    // A mapping (ATRANS): chunk tid>>7, kk (tid>>3)&15, r8 (tid&7)*8
    const int at_t = tid >> 7, at_kk = (tid >> 3) & 15, at_b = (tid & 7) * 8;
    // B mapping: row = tid>>4 (0..15), col8 = (tid&15)*8
    const int bRow = tid >> 4, bCol = (tid & 15) * 8;

    float4 A0, A1, B0, B1;

    auto loadT = [&](int k0) {
        if (!ATRANS) {
            const float* p = A + (size_t)(by * BM + aRow) * K + k0 + aC;
            A0 = *(const float4*)(p);
            A1 = *(const float4*)(p + 4);
        } else {
            const float* p = A + ((size_t)(by * 2 + at_t) * K + (k0 + at_kk)) * 64 + at_b;
            A0 = *(const float4*)(p);
            A1 = *(const float4*)(p + 4);
        }
        const float* pb = B + (size_t)(k0 + bRow) * N + bx * BN + bCol;
        B0 = *(const float4*)(pb);
        B1 = *(const float4*)(pb + 4);
    };
    auto storeT = [&](int buf) {
        if (!ATRANS) {
            As[buf][aC + 0][aRow] = A0.x; As[buf][aC + 1][aRow] = A0.y;
            As[buf][aC + 2][aRow] = A0.z; As[buf][aC + 3][aRow] = A0.w;
            As[buf][aC + 4][aRow] = A1.x; As[buf][aC + 5][aRow] = A1.y;
            As[buf][aC + 6][aRow] = A1.z; As[buf][aC + 7][aRow] = A1.w;
        } else {
            *(float4*)&As[buf][at_kk][at_t * 64 + at_b]     = A0;
            *(float4*)&As[buf][at_kk][at_t * 64 + at_b + 4] = A1;
        }
        *(float4*)&Bs[buf][bRow][bCol]     = B0;
        *(float4*)&Bs[buf][bRow][bCol + 4] = B1;
    };

    loadT(0);
    storeT(0);
    __syncthreads();

    const int nIter = K / BK;
    for (int it = 0; it < nIter; ++it) {
        const int cur = it & 1;
        if (it + 1 < nIter) loadT((it + 1) * BK);

#pragma unroll
        for (int kk = 0; kk < BK; kk++) {
            float4 alo = *(const float4*)&As[cur][kk][ty * 8];
            float4 ahi = *(const float4*)&As[cur][kk][ty * 8 + 4];
            ulonglong2 b01 = *(const ulonglong2*)&Bs[cur][kk][tx * 8];
            ulonglong2 b23 = *(const ulonglong2*)&Bs[cur][kk][tx * 8 + 4];
            float a[8] = {alo.x, alo.y, alo.z, alo.w, ahi.x, ahi.y, ahi.z, ahi.w};
#pragma unroll
            for (int i = 0; i < 8; i++) {
                u64 ad = pack2(a[i], a[i]);
                acc[i][0] = fma2(ad, b01.x, acc[i][0]);
                acc[i][1] = fma2(ad, b01.y, acc[i][1]);
                acc[i][2] = fma2(ad, b23.x, acc[i][2]);
                acc[i][3] = fma2(ad, b23.y, acc[i][3]);
            }
        }
        if (it + 1 < nIter) storeT(cur ^ 1);
        __syncthreads();
    }

    const int row0 = by * BM + ty * 8, col0 = bx * BN + tx * 8;
#pragma unroll
    for (int i = 0; i < 8; i++) {
        float out[8];
#pragma unroll
        for (int j = 0; j < 4; j++) {
            float2 f = unpack2(acc[i][j]);
            out[2 * j] = f.x; out[2 * j + 1] = f.y;
        }
#pragma unroll
        for (int j = 0; j < 8; j++) {
            float v = out[j] + bias[col0 + j];
            if (LEAKY) v = v >= 0.f ? v : 0.01f * v;
            out[j] = v;
        }
        *(float4*)&C[(size_t)(row0 + i) * N + col0]     = make_float4(out[0], out[1], out[2], out[3]);
        *(float4*)&C[(size_t)(row0 + i) * N + col0 + 4] = make_float4(out[4], out[5], out[6], out[7]);
    }
}

// ---------------------------------------------------------------------------
__global__ void transpose_h0(const float* __restrict__ in, float* __restrict__ out) {
    int i = blockIdx.x * 256 + threadIdx.x;        // 65536
    int c = i >> 6, r = i & 63;
    out[i] = in[(size_t)r * HID + c];              // out[c][r]
}
__global__ void transpose_hfinal(const float* __restrict__ hsTlast, float* __restrict__ out) {
    int i = blockIdx.x * 256 + threadIdx.x;        // 65536
    int r = i >> 10, c = i & 1023;
    out[i] = hsTlast[(size_t)c * 64 + r];          // out[r][c]
}

// ---------------------------------------------------------------------------
extern "C" void kernel_launch(void* const* d_in, const int* in_sizes, int n_in,
                              void* d_out, int out_size)
{
    const float* x   = (const float*)d_in[0];
    const float* h0  = (const float*)d_in[1];
    const float* i_h = (const float*)d_in[2];
    const float* h_h = (const float*)d_in[3];
    const float* h_o = (const float*)d_in[4];
    const float* b_i = (const float*)d_in[5];
    const float* b_o = (const float*)d_in[6];
    float* out = (float*)d_out;

    float *xi = nullptr, *hsT = nullptr, *h0T = nullptr;
    cudaGetSymbolAddress((void**)&xi,  g_xi);
    cudaGetSymbolAddress((void**)&hsT, g_hsT);
    cudaGetSymbolAddress((void**)&h0T, g_h0T);

    static int smem_set = 0;
    if (!smem_set) {
        cudaFuncSetAttribute(rnn_scan, cudaFuncAttributeMaxDynamicSharedMemorySize, 81920);
        smem_set = 1;
    }

    // 0) transpose h0 -> [c][r]
    transpose_h0<<<256, 256>>>(h0, h0T);

    // 1) xi = x @ i_h + b_i : [32768,512]@[512,1024]
    {
        dim3 grid(HID / 128, (SEQL * BATCH) / 128);
        sgemm_db<false, false><<<grid, 256>>>(x, i_h, b_i, xi, SEQL * BATCH, HID, INF);
    }

    // 2) persistent scan (all 512 steps in one launch)
    rnn_scan<<<NBLK, SCAN_THREADS, 81920>>>(h0T, h_h, xi, hsT);

    // 3) outputs = leaky_relu(hsT @ h_o + b_o) : [32768,1024]@[1024,512]
    {
        dim3 grid(OUTF / 128, (SEQL * BATCH) / 128);
        sgemm_db<true, true><<<grid, 256>>>(hsT, h_o, b_o, out, SEQL * BATCH, OUTF, HID);
    }

    // 4) h_final = transpose(hsT[511])
    transpose_hfinal<<<256, 256>>>(hsT + (size_t)(SEQL - 1) * BATCH * HID,
                                   out + (size_t)SEQL * BATCH * OUTF);
}

// round 5
// speedup vs baseline: 1.2404x; 1.0917x over previous
#include <cuda_runtime.h>
#include <math.h>

#define SEQL 512
#define BATCH 64
#define INF 512
#define HID 1024
#define OUTF 512
#define NBLK 128
#define SCAN_THREADS 512

typedef unsigned long long u64;

// Scratch (device globals; allocation-free)
__device__ float g_xi [(size_t)SEQL * BATCH * HID];   // [t][b][c] row-major
__device__ float g_hsT[(size_t)SEQL * BATCH * HID];   // [t][c][r] transposed
__device__ float g_h0T[(size_t)BATCH * HID];          // [c][r]
__device__ unsigned g_count = 0;                      // monotonic barrier counter

// ---------------- f32x2 helpers ----------------
__device__ __forceinline__ u64 pack2(float x, float y) {
    u64 d; asm("mov.b64 %0,{%1,%2};" : "=l"(d) : "f"(x), "f"(y)); return d;
}
__device__ __forceinline__ float2 unpack2(u64 d) {
    float2 v; asm("mov.b64 {%0,%1},%2;" : "=f"(v.x), "=f"(v.y) : "l"(d)); return v;
}
__device__ __forceinline__ u64 fma2(u64 a, u64 b, u64 c) {
    u64 d; asm("fma.rn.f32x2 %0,%1,%2,%3;" : "=l"(d) : "l"(a), "l"(b), "l"(c)); return d;
}
__device__ __forceinline__ u64 add2(u64 a, u64 b) {
    u64 d; asm("add.rn.f32x2 %0,%1,%2;" : "=l"(d) : "l"(a), "l"(b)); return d;
}

// ---------------------------------------------------------------------------
// Persistent scan: h_t = tanh(xi_t + h_{t-1} @ W). 128 blocks x 512 threads.
// Block b owns output cols [8b, 8b+8); W slice (1024x8) in SMEM as dup pairs.
// 16 warps = 8 k-splits x 2 row-halves; lane tile 4 rows x 2 cols.
// Inner loop: register double-buffered chunks of 8 k (8 LDG.128 in flight).
// Barrier: leaderless red.release + warp-0 poll of monotonic counter.
// ---------------------------------------------------------------------------
__global__ void __launch_bounds__(SCAN_THREADS, 1) rnn_scan(
    const float* __restrict__ h0T, const float* __restrict__ W,
    const float* __restrict__ xi, float* __restrict__ hsT)
{
    extern __shared__ u64 smdyn[];
    u64* wS2  = smdyn;           // [1024][8] dup pairs = 64KB
    u64* sRed = smdyn + 8192;    // [8 ksplit][8 col][32 rowpair] = 16KB

    const int tid = threadIdx.x;
    const int cb  = blockIdx.x * 8;

    for (int i = tid; i < 8192; i += SCAN_THREADS) {
        int k = i >> 3, c = i & 7;
        float w = W[(size_t)k * HID + cb + c];
        wS2[i] = pack2(w, w);
    }
    __syncthreads();

    const int wg   = tid >> 5, l = tid & 31;
    const int q    = wg >> 1;          // k-split 0..7
    const int half = wg & 1;           // row half
    const int qd   = l & 7;
    const int cg   = l >> 3;           // col pair 0..3
    const int rowoff = half * 32 + qd * 4;
    const int kbeg = q * 128;

    const int rp2 = tid & 31;          // reduction role (tid<256)
    const int rc  = tid >> 5;          // local col 0..7

    unsigned* cnt = &g_count;

    for (int t = 0; t < SEQL; ++t) {
        // ---- prefetch xi for this step's epilogue (hidden under GEMM) ----
        float x0 = 0.f, x1 = 0.f;
        if (tid < 256) {
            const float* xit = xi + (size_t)t * BATCH * HID;
            x0 = __ldg(&xit[(size_t)(2 * rp2)     * HID + cb + rc]);
            x1 = __ldg(&xit[(size_t)(2 * rp2 + 1) * HID + cb + rc]);
        }

        const float* hin = t ? hsT + (size_t)(t - 1) * BATCH * HID : h0T;
        const float* hp = hin + (size_t)kbeg * 64 + rowoff;
        const u64*   wp = wS2 + (size_t)kbeg * 8 + 2 * cg;

        u64 a0 = 0, a1 = 0, a2 = 0, a3 = 0;

        // chunked register double-buffer: 16 chunks x 8 k
        ulonglong2 hbuf[8];
#pragma unroll
        for (int j = 0; j < 8; ++j)
            hbuf[j] = *(const ulonglong2*)(hp + (size_t)j * 64);

#pragma unroll 1
        for (int c = 0; c < 15; ++c) {
            ulonglong2 hnext[8];
#pragma unroll
            for (int j = 0; j < 8; ++j)
                hnext[j] = *(const ulonglong2*)(hp + (size_t)((c + 1) * 8 + j) * 64);
#pragma unroll
            for (int j = 0; j < 8; ++j) {
                ulonglong2 wv = *(const ulonglong2*)(wp + (size_t)(c * 8 + j) * 8);
                a0 = fma2(hbuf[j].x, wv.x, a0);
                a1 = fma2(hbuf[j].y, wv.x, a1);
                a2 = fma2(hbuf[j].x, wv.y, a2);
                a3 = fma2(hbuf[j].y, wv.y, a3);
            }
#pragma unroll
            for (int j = 0; j < 8; ++j) hbuf[j] = hnext[j];
        }
#pragma unroll
        for (int j = 0; j < 8; ++j) {
            ulonglong2 wv = *(const ulonglong2*)(wp + (size_t)(15 * 8 + j) * 8);
            a0 = fma2(hbuf[j].x, wv.x, a0);
            a1 = fma2(hbuf[j].y, wv.x, a1);
            a2 = fma2(hbuf[j].x, wv.y, a2);
            a3 = fma2(hbuf[j].y, wv.y, a3);
        }

        {
            int rp = half * 16 + qd * 2;
            sRed[((size_t)q * 8 + 2 * cg)     * 32 + rp    ] = a0;
            sRed[((size_t)q * 8 + 2 * cg)     * 32 + rp + 1] = a1;
            sRed[((size_t)q * 8 + 2 * cg + 1) * 32 + rp    ] = a2;
            sRed[((size_t)q * 8 + 2 * cg + 1) * 32 + rp + 1] = a3;
        }
        __syncthreads();

        if (tid < 256) {
            u64 s = sRed[(size_t)rc * 32 + rp2];
#pragma unroll
            for (int qq = 1; qq < 8; ++qq)
                s = add2(s, sRed[((size_t)qq * 8 + rc) * 32 + rp2]);
            float2 f = unpack2(s);
            float v0 = tanhf(f.x + x0);
            float v1 = tanhf(f.y + x1);
            *(u64*)(hsT + (size_t)t * BATCH * HID + (size_t)(cb + rc) * 64 + 2 * rp2)
                = pack2(v0, v1);
        }

        // ---- grid barrier: release-increment + poll monotonic counter ----
        __syncthreads();                      // all stores of h_t issued
        if (tid == 0) {
            asm volatile("red.release.gpu.global.add.u32 [%0], 1;"
                         :: "l"(cnt) : "memory");
        }
        if (tid < 32) {
            const unsigned target = (unsigned)NBLK * (unsigned)(t + 1);
            unsigned cur;
            do {
                asm volatile("ld.acquire.gpu.u32 %0,[%1];"
                             : "=r"(cur) : "l"(cnt) : "memory");
            } while (cur < target);
        }
        __syncthreads();
    }
}

// ---------------------------------------------------------------------------
// Double-buffered 128x128x16 f32x2 GEMM: C = A @ B + bias, optional leaky.
// ATRANS: A stored as [M/64][K][64] (transposed hidden-state history).
// ---------------------------------------------------------------------------
template <bool ATRANS, bool LEAKY>
__global__ __launch_bounds__(256) void sgemm_db(
    const float* __restrict__ A, const float* __restrict__ B,
    const float* __restrict__ bias, float* __restrict__ C,
    int M, int N, int K)
{
    constexpr int BM = 128, BN = 128, BK = 16;
    __shared__ __align__(16) float As[2][BK][BM];
    __shared__ __align__(16) float Bs[2][BK][BN];

    const int tid = threadIdx.x;
    const int bx = blockIdx.x, by = blockIdx.y;
    const int tx = tid & 15, ty = tid >> 4;

    u64 acc[8][4];
#pragma unroll
    for (int i = 0; i < 8; i++)
#pragma unroll
        for (int j = 0; j < 4; j++) acc[i][j] = 0ull;

    const int aRow = tid >> 1, aC = (tid & 1) * 8;
    const int at_t = tid >> 7, at_kk = (tid >> 3) & 15, at_b = (tid & 7) * 8;
    const int bRow = tid >> 4, bCol = (tid & 15) * 8;

    float4 A0, A1, B0, B1;

    auto loadT = [&](int k0) {
        if (!ATRANS) {
            const float* p = A + (size_t)(by * BM + aRow) * K + k0 + aC;
            A0 = *(const float4*)(p);
            A1 = *(const float4*)(p + 4);
        } else {
            const float* p = A + ((size_t)(by * 2 + at_t) * K + (k0 + at_kk)) * 64 + at_b;
            A0 = *(const float4*)(p);
            A1 = *(const float4*)(p + 4);
        }
        const float* pb = B + (size_t)(k0 + bRow) * N + bx * BN + bCol;
        B0 = *(const float4*)(pb);
        B1 = *(const float4*)(pb + 4);
    };
    auto storeT = [&](int buf) {
        if (!ATRANS) {
            As[buf][aC + 0][aRow] = A0.x; As[buf][aC + 1][aRow] = A0.y;
            As[buf][aC + 2][aRow] = A0.z; As[buf][aC + 3][aRow] = A0.w;
            As[buf][aC + 4][aRow] = A1.x; As[buf][aC + 5][aRow] = A1.y;
            As[buf][aC + 6][aRow] = A1.z; As[buf][aC + 7][aRow] = A1.w;
        } else {
            *(float4*)&As[buf][at_kk][at_t * 64 + at_b]     = A0;
            *(float4*)&As[buf][at_kk][at_t * 64 + at_b + 4] = A1;
        }
        *(float4*)&Bs[buf][bRow][bCol]     = B0;
        *(float4*)&Bs[buf][bRow][bCol + 4] = B1;
    };

    loadT(0);
    storeT(0);
    __syncthreads();

    const int nIter = K / BK;
    for (int it = 0; it < nIter; ++it) {
        const int cur = it & 1;
        if (it + 1 < nIter) loadT((it + 1) * BK);

#pragma unroll
        for (int kk = 0; kk < BK; kk++) {
            float4 alo = *(const float4*)&As[cur][kk][ty * 8];
            float4 ahi = *(const float4*)&As[cur][kk][ty * 8 + 4];
            ulonglong2 b01 = *(const ulonglong2*)&Bs[cur][kk][tx * 8];
            ulonglong2 b23 = *(const ulonglong2*)&Bs[cur][kk][tx * 8 + 4];
            float a[8] = {alo.x, alo.y, alo.z, alo.w, ahi.x, ahi.y, ahi.z, ahi.w};
#pragma unroll
            for (int i = 0; i < 8; i++) {
                u64 ad = pack2(a[i], a[i]);
                acc[i][0] = fma2(ad, b01.x, acc[i][0]);
                acc[i][1] = fma2(ad, b01.y, acc[i][1]);
                acc[i][2] = fma2(ad, b23.x, acc[i][2]);
                acc[i][3] = fma2(ad, b23.y, acc[i][3]);
            }
        }
        if (it + 1 < nIter) storeT(cur ^ 1);
        __syncthreads();
    }

    const int row0 = by * BM + ty * 8, col0 = bx * BN + tx * 8;
#pragma unroll
    for (int i = 0; i < 8; i++) {
        float out[8];
#pragma unroll
        for (int j = 0; j < 4; j++) {
            float2 f = unpack2(acc[i][j]);
            out[2 * j] = f.x; out[2 * j + 1] = f.y;
        }
#pragma unroll
        for (int j = 0; j < 8; j++) {
            float v = out[j] + bias[col0 + j];
            if (LEAKY) v = v >= 0.f ? v : 0.01f * v;
            out[j] = v;
        }
        *(float4*)&C[(size_t)(row0 + i) * N + col0]     = make_float4(out[0], out[1], out[2], out[3]);
        *(float4*)&C[(size_t)(row0 + i) * N + col0 + 4] = make_float4(out[4], out[5], out[6], out[7]);
    }
}

// ---------------------------------------------------------------------------
__global__ void transpose_h0(const float* __restrict__ in, float* __restrict__ out) {
    int i = blockIdx.x * 256 + threadIdx.x;        // 65536
    int c = i >> 6, r = i & 63;
    out[i] = in[(size_t)r * HID + c];              // out[c][r]
}
// Also resets the scan barrier counter for the next launch (stream-ordered).
__global__ void transpose_hfinal(const float* __restrict__ hsTlast, float* __restrict__ out) {
    int i = blockIdx.x * 256 + threadIdx.x;        // 65536
    int r = i >> 10, c = i & 1023;
    out[i] = hsTlast[(size_t)c * 64 + r];          // out[r][c]
    if (i == 0) g_count = 0;
}

// ---------------------------------------------------------------------------
extern "C" void kernel_launch(void* const* d_in, const int* in_sizes, int n_in,
                              void* d_out, int out_size)
{
    const float* x   = (const float*)d_in[0];
    const float* h0  = (const float*)d_in[1];
    const float* i_h = (const float*)d_in[2];
    const float* h_h = (const float*)d_in[3];
    const float* h_o = (const float*)d_in[4];
    const float* b_i = (const float*)d_in[5];
    const float* b_o = (const float*)d_in[6];
    float* out = (float*)d_out;

    float *xi = nullptr, *hsT = nullptr, *h0T = nullptr;
    cudaGetSymbolAddress((void**)&xi,  g_xi);
    cudaGetSymbolAddress((void**)&hsT, g_hsT);
    cudaGetSymbolAddress((void**)&h0T, g_h0T);

    static int smem_set = 0;
    if (!smem_set) {
        cudaFuncSetAttribute(rnn_scan, cudaFuncAttributeMaxDynamicSharedMemorySize, 81920);
        smem_set = 1;
    }

    // 0) transpose h0 -> [c][r]
    transpose_h0<<<256, 256>>>(h0, h0T);

    // 1) xi = x @ i_h + b_i : [32768,512]@[512,1024]
    {
        dim3 grid(HID / 128, (SEQL * BATCH) / 128);
        sgemm_db<false, false><<<grid, 256>>>(x, i_h, b_i, xi, SEQL * BATCH, HID, INF);
    }

    // 2) persistent scan (all 512 steps in one launch)
    rnn_scan<<<NBLK, SCAN_THREADS, 81920>>>(h0T, h_h, xi, hsT);

    // 3) outputs = leaky_relu(hsT @ h_o + b_o) : [32768,1024]@[1024,512]
    {
        dim3 grid(OUTF / 128, (SEQL * BATCH) / 128);
        sgemm_db<true, true><<<grid, 256>>>(hsT, h_o, b_o, out, SEQL * BATCH, OUTF, HID);
    }

    // 4) h_final = transpose(hsT[511])  (+ barrier counter reset)
    transpose_hfinal<<<256, 256>>>(hsT + (size_t)(SEQL - 1) * BATCH * HID,
                                   out + (size_t)SEQL * BATCH * OUTF);
}

// round 6
// speedup vs baseline: 1.2458x; 1.0043x over previous
#include <cuda_runtime.h>
#include <math.h>

#define SEQL 512
#define BATCH 64
#define INF 512
#define HID 1024
#define OUTF 512
#define NBLK 128
#define SCAN_THREADS 512

typedef unsigned long long u64;

// Scratch (device globals; allocation-free)
__device__ float g_xi [(size_t)SEQL * BATCH * HID];   // [t][b][c] row-major
__device__ float g_hsT[(size_t)SEQL * BATCH * HID];   // [t][c][r] transposed
__device__ float g_h0T[(size_t)BATCH * HID];          // [c][r]
__device__ unsigned g_count = 0;                      // monotonic barrier counter

// ---------------- f32x2 helpers ----------------
__device__ __forceinline__ u64 pack2(float x, float y) {
    u64 d; asm("mov.b64 %0,{%1,%2};" : "=l"(d) : "f"(x), "f"(y)); return d;
}
__device__ __forceinline__ float2 unpack2(u64 d) {
    float2 v; asm("mov.b64 {%0,%1},%2;" : "=f"(v.x), "=f"(v.y) : "l"(d)); return v;
}
__device__ __forceinline__ u64 fma2(u64 a, u64 b, u64 c) {
    u64 d; asm("fma.rn.f32x2 %0,%1,%2,%3;" : "=l"(d) : "l"(a), "l"(b), "l"(c)); return d;
}
__device__ __forceinline__ u64 add2(u64 a, u64 b) {
    u64 d; asm("add.rn.f32x2 %0,%1,%2;" : "=l"(d) : "l"(a), "l"(b)); return d;
}

// ---------------------------------------------------------------------------
// Persistent scan: h_t = tanh(xi_t + h_{t-1} @ W). 128 blocks x 512 threads.
// Block b owns output cols [8b, 8b+8); W slice (1024x8) in SMEM as dup pairs.
// 16 warps = 8 k-splits x 2 row-halves; lane tile 4 rows x 2 cols.
// Inner loop: depth-4 software pipeline of 4-k chunks (12 LDG.128 in flight,
// each buffer refilled 3 compute-chunks (~240cyc) before reuse -> L2 latency
// fully covered).
// ---------------------------------------------------------------------------
__global__ void __launch_bounds__(SCAN_THREADS, 1) rnn_scan(
    const float* __restrict__ h0T, const float* __restrict__ W,
    const float* __restrict__ xi, float* __restrict__ hsT)
{
    extern __shared__ u64 smdyn[];
    u64* wS2  = smdyn;           // [1024][8] dup pairs = 64KB
    u64* sRed = smdyn + 8192;    // [8 ksplit][8 col][32 rowpair] = 16KB

    const int tid = threadIdx.x;
    const int cb  = blockIdx.x * 8;

    for (int i = tid; i < 8192; i += SCAN_THREADS) {
        int k = i >> 3, c = i & 7;
        float w = W[(size_t)k * HID + cb + c];
        wS2[i] = pack2(w, w);
    }
    __syncthreads();

    const int wg   = tid >> 5, l = tid & 31;
    const int q    = wg >> 1;          // k-split 0..7
    const int half = wg & 1;           // row half
    const int qd   = l & 7;
    const int cg   = l >> 3;           // col pair 0..3
    const int rowoff = half * 32 + qd * 4;
    const int kbeg = q * 128;

    const int rp2 = tid & 31;          // reduction role (tid<256)
    const int rc  = tid >> 5;          // local col 0..7

    unsigned* cnt = &g_count;

    for (int t = 0; t < SEQL; ++t) {
        // ---- prefetch xi for this step's epilogue (hidden under GEMM) ----
        float x0 = 0.f, x1 = 0.f;
        if (tid < 256) {
            const float* xit = xi + (size_t)t * BATCH * HID;
            x0 = __ldg(&xit[(size_t)(2 * rp2)     * HID + cb + rc]);
            x1 = __ldg(&xit[(size_t)(2 * rp2 + 1) * HID + cb + rc]);
        }

        const float* hin = t ? hsT + (size_t)(t - 1) * BATCH * HID : h0T;
        const float* hp = hin + (size_t)kbeg * 64 + rowoff;
        const u64*   wp = wS2 + (size_t)kbeg * 8 + 2 * cg;

        u64 a0 = 0, a1 = 0, a2 = 0, a3 = 0;

        // depth-4 software pipeline, 32 chunks x 4 k
        ulonglong2 hbuf[4][4];
#pragma unroll
        for (int c = 0; c < 4; ++c)
#pragma unroll
            for (int j = 0; j < 4; ++j)
                hbuf[c][j] = *(const ulonglong2*)(hp + (size_t)(c * 4 + j) * 64);

#pragma unroll 4
        for (int c = 0; c < 32; ++c) {
            const int cur = c & 3;
#pragma unroll
            for (int j = 0; j < 4; ++j) {
                ulonglong2 wv = *(const ulonglong2*)(wp + (size_t)(c * 4 + j) * 8);
                a0 = fma2(hbuf[cur][j].x, wv.x, a0);
                a1 = fma2(hbuf[cur][j].y, wv.x, a1);
                a2 = fma2(hbuf[cur][j].x, wv.y, a2);
                a3 = fma2(hbuf[cur][j].y, wv.y, a3);
            }
            if (c + 4 < 32) {
#pragma unroll
                for (int j = 0; j < 4; ++j)
                    hbuf[cur][j] = *(const ulonglong2*)(hp + (size_t)((c + 4) * 4 + j) * 64);
            }
        }

        {
            int rp = half * 16 + qd * 2;
            sRed[((size_t)q * 8 + 2 * cg)     * 32 + rp    ] = a0;
            sRed[((size_t)q * 8 + 2 * cg)     * 32 + rp + 1] = a1;
            sRed[((size_t)q * 8 + 2 * cg + 1) * 32 + rp    ] = a2;
            sRed[((size_t)q * 8 + 2 * cg + 1) * 32 + rp + 1] = a3;
        }
        __syncthreads();

        if (tid < 256) {
            u64 s = sRed[(size_t)rc * 32 + rp2];
#pragma unroll
            for (int qq = 1; qq < 8; ++qq)
                s = add2(s, sRed[((size_t)qq * 8 + rc) * 32 + rp2]);
            float2 f = unpack2(s);
            float v0 = tanhf(f.x + x0);
            float v1 = tanhf(f.y + x1);
            *(u64*)(hsT + (size_t)t * BATCH * HID + (size_t)(cb + rc) * 64 + 2 * rp2)
                = pack2(v0, v1);
        }

        // ---- grid barrier: release-increment + poll monotonic counter ----
        __syncthreads();                      // all stores of h_t issued
        if (tid == 0) {
            asm volatile("red.release.gpu.global.add.u32 [%0], 1;"
                         :: "l"(cnt) : "memory");
        }
        if (tid < 32) {
            const unsigned target = (unsigned)NBLK * (unsigned)(t + 1);
            unsigned cur;
            do {
                asm volatile("ld.acquire.gpu.u32 %0,[%1];"
                             : "=r"(cur) : "l"(cnt) : "memory");
            } while (cur < target);
        }
        __syncthreads();
    }
}

// ---------------------------------------------------------------------------
// Double-buffered 128x128x16 f32x2 GEMM: C = A @ B + bias, optional leaky.
// ATRANS: A stored as [M/64][K][64] (transposed hidden-state history).
// ---------------------------------------------------------------------------
template <bool ATRANS, bool LEAKY>
__global__ __launch_bounds__(256) void sgemm_db(
    const float* __restrict__ A, const float* __restrict__ B,
    const float* __restrict__ bias, float* __restrict__ C,
    int M, int N, int K)
{
    constexpr int BM = 128, BN = 128, BK = 16;
    __shared__ __align__(16) float As[2][BK][BM];
    __shared__ __align__(16) float Bs[2][BK][BN];

    const int tid = threadIdx.x;
    const int bx = blockIdx.x, by = blockIdx.y;
    const int tx = tid & 15, ty = tid >> 4;

    u64 acc[8][4];
#pragma unroll
    for (int i = 0; i < 8; i++)
#pragma unroll
        for (int j = 0; j < 4; j++) acc[i][j] = 0ull;

    const int aRow = tid >> 1, aC = (tid & 1) * 8;
    const int at_t = tid >> 7, at_kk = (tid >> 3) & 15, at_b = (tid & 7) * 8;
    const int bRow = tid >> 4, bCol = (tid & 15) * 8;

    float4 A0, A1, B0, B1;

    auto loadT = [&](int k0) {
        if (!ATRANS) {
            const float* p = A + (size_t)(by * BM + aRow) * K + k0 + aC;
            A0 = *(const float4*)(p);
            A1 = *(const float4*)(p + 4);
        } else {
            const float* p = A + ((size_t)(by * 2 + at_t) * K + (k0 + at_kk)) * 64 + at_b;
            A0 = *(const float4*)(p);
            A1 = *(const float4*)(p + 4);
        }
        const float* pb = B + (size_t)(k0 + bRow) * N + bx * BN + bCol;
        B0 = *(const float4*)(pb);
        B1 = *(const float4*)(pb + 4);
    };
    auto storeT = [&](int buf) {
        if (!ATRANS) {
            As[buf][aC + 0][aRow] = A0.x; As[buf][aC + 1][aRow] = A0.y;
            As[buf][aC + 2][aRow] = A0.z; As[buf][aC + 3][aRow] = A0.w;
            As[buf][aC + 4][aRow] = A1.x; As[buf][aC + 5][aRow] = A1.y;
            As[buf][aC + 6][aRow] = A1.z; As[buf][aC + 7][aRow] = A1.w;
        } else {
            *(float4*)&As[buf][at_kk][at_t * 64 + at_b]     = A0;
            *(float4*)&As[buf][at_kk][at_t * 64 + at_b + 4] = A1;
        }
        *(float4*)&Bs[buf][bRow][bCol]     = B0;
        *(float4*)&Bs[buf][bRow][bCol + 4] = B1;
    };

    loadT(0);
    storeT(0);
    __syncthreads();

    const int nIter = K / BK;
    for (int it = 0; it < nIter; ++it) {
        const int cur = it & 1;
        if (it + 1 < nIter) loadT((it + 1) * BK);

#pragma unroll
        for (int kk = 0; kk < BK; kk++) {
            float4 alo = *(const float4*)&As[cur][kk][ty * 8];
            float4 ahi = *(const float4*)&As[cur][kk][ty * 8 + 4];
            ulonglong2 b01 = *(const ulonglong2*)&Bs[cur][kk][tx * 8];
            ulonglong2 b23 = *(const ulonglong2*)&Bs[cur][kk][tx * 8 + 4];
            float a[8] = {alo.x, alo.y, alo.z, alo.w, ahi.x, ahi.y, ahi.z, ahi.w};
#pragma unroll
            for (int i = 0; i < 8; i++) {
                u64 ad = pack2(a[i], a[i]);
                acc[i][0] = fma2(ad, b01.x, acc[i][0]);
                acc[i][1] = fma2(ad, b01.y, acc[i][1]);
                acc[i][2] = fma2(ad, b23.x, acc[i][2]);
                acc[i][3] = fma2(ad, b23.y, acc[i][3]);
            }
        }
        if (it + 1 < nIter) storeT(cur ^ 1);
        __syncthreads();
    }

    const int row0 = by * BM + ty * 8, col0 = bx * BN + tx * 8;
#pragma unroll
    for (int i = 0; i < 8; i++) {
        float out[8];
#pragma unroll
        for (int j = 0; j < 4; j++) {
            float2 f = unpack2(acc[i][j]);
            out[2 * j] = f.x; out[2 * j + 1] = f.y;
        }
#pragma unroll
        for (int j = 0; j < 8; j++) {
            float v = out[j] + bias[col0 + j];
            if (LEAKY) v = v >= 0.f ? v : 0.01f * v;
            out[j] = v;
        }
        *(float4*)&C[(size_t)(row0 + i) * N + col0]     = make_float4(out[0], out[1], out[2], out[3]);
        *(float4*)&C[(size_t)(row0 + i) * N + col0 + 4] = make_float4(out[4], out[5], out[6], out[7]);
    }
}

// ---------------------------------------------------------------------------
__global__ void transpose_h0(const float* __restrict__ in, float* __restrict__ out) {
    int i = blockIdx.x * 256 + threadIdx.x;        // 65536
    int c = i >> 6, r = i & 63;
    out[i] = in[(size_t)r * HID + c];              // out[c][r]
}
// Also resets the scan barrier counter for the next launch (stream-ordered).
__global__ void transpose_hfinal(const float* __restrict__ hsTlast, float* __restrict__ out) {
    int i = blockIdx.x * 256 + threadIdx.x;        // 65536
    int r = i >> 10, c = i & 1023;
    out[i] = hsTlast[(size_t)c * 64 + r];          // out[r][c]
    if (i == 0) g_count = 0;
}

// ---------------------------------------------------------------------------
extern "C" void kernel_launch(void* const* d_in, const int* in_sizes, int n_in,
                              void* d_out, int out_size)
{
    const float* x   = (const float*)d_in[0];
    const float* h0  = (const float*)d_in[1];
    const float* i_h = (const float*)d_in[2];
    const float* h_h = (const float*)d_in[3];
    const float* h_o = (const float*)d_in[4];
    const float* b_i = (const float*)d_in[5];
    const float* b_o = (const float*)d_in[6];
    float* out = (float*)d_out;

    float *xi = nullptr, *hsT = nullptr, *h0T = nullptr;
    cudaGetSymbolAddress((void**)&xi,  g_xi);
    cudaGetSymbolAddress((void**)&hsT, g_hsT);
    cudaGetSymbolAddress((void**)&h0T, g_h0T);

    static int smem_set = 0;
    if (!smem_set) {
        cudaFuncSetAttribute(rnn_scan, cudaFuncAttributeMaxDynamicSharedMemorySize, 81920);
        smem_set = 1;
    }

    // 0) transpose h0 -> [c][r]
    transpose_h0<<<256, 256>>>(h0, h0T);

    // 1) xi = x @ i_h + b_i : [32768,512]@[512,1024]
    {
        dim3 grid(HID / 128, (SEQL * BATCH) / 128);
        sgemm_db<false, false><<<grid, 256>>>(x, i_h, b_i, xi, SEQL * BATCH, HID, INF);
    }

    // 2) persistent scan (all 512 steps in one launch)
    rnn_scan<<<NBLK, SCAN_THREADS, 81920>>>(h0T, h_h, xi, hsT);

    // 3) outputs = leaky_relu(hsT @ h_o + b_o) : [32768,1024]@[1024,512]
    {
        dim3 grid(OUTF / 128, (SEQL * BATCH) / 128);
        sgemm_db<true, true><<<grid, 256>>>(hsT, h_o, b_o, out, SEQL * BATCH, OUTF, HID);
    }

    // 4) h_final = transpose(hsT[511])  (+ barrier counter reset)
    transpose_hfinal<<<256, 256>>>(hsT + (size_t)(SEQL - 1) * BATCH * HID,
                                   out + (size_t)SEQL * BATCH * OUTF);
}

// round 7
// speedup vs baseline: 1.3890x; 1.1150x over previous
#include <cuda_runtime.h>
#include <math.h>

#define SEQL 512
#define BATCH 64
#define INF 512
#define HID 1024
#define OUTF 512
#define NBLK 128
#define SCAN_THREADS 512

typedef unsigned long long u64;

// Scratch (device globals; allocation-free)
__device__ float g_xi [(size_t)SEQL * BATCH * HID];   // [t][b][c] row-major
__device__ float g_hsT[(size_t)SEQL * BATCH * HID];   // [t][c][r] transposed
__device__ float g_h0T[(size_t)BATCH * HID];          // [c][r]
__device__ unsigned g_count = 0;                      // monotonic barrier counter

// ---------------- f32x2 helpers ----------------
__device__ __forceinline__ u64 pack2(float x, float y) {
    u64 d; asm("mov.b64 %0,{%1,%2};" : "=l"(d) : "f"(x), "f"(y)); return d;
}
__device__ __forceinline__ float2 unpack2(u64 d) {
    float2 v; asm("mov.b64 {%0,%1},%2;" : "=f"(v.x), "=f"(v.y) : "l"(d)); return v;
}
__device__ __forceinline__ u64 fma2(u64 a, u64 b, u64 c) {
    u64 d; asm("fma.rn.f32x2 %0,%1,%2,%3;" : "=l"(d) : "l"(a), "l"(b), "l"(c)); return d;
}
__device__ __forceinline__ u64 add2(u64 a, u64 b) {
    u64 d; asm("add.rn.f32x2 %0,%1,%2;" : "=l"(d) : "l"(a), "l"(b)); return d;
}

// ---------------------------------------------------------------------------
// Persistent scan: h_t = tanh(xi_t + h_{t-1} @ W).
// 128 blocks = 64 colgroups(16 cols) x 2 rowgroups(32 rows); 512 threads.
// Block reads only its 32 rows of h (128KB/step -> 16MB/step chip-wide).
// W slice [1024][16] lives in SMEM as dup'd f32x2 pairs (128KB).
// 16 warps = 16 k-splits (64 k each); lane tile 8 rows x 2 cols.
// sRed padded (stride 17) to avoid STS bank conflicts; leaderless barrier.
// ---------------------------------------------------------------------------
__global__ void __launch_bounds__(SCAN_THREADS, 1) rnn_scan(
    const float* __restrict__ h0T, const float* __restrict__ W,
    const float* __restrict__ xi, float* __restrict__ hsT)
{
    extern __shared__ u64 smdyn[];
    u64* wS2  = smdyn;            // [1024][16] dup pairs = 128KB
    u64* sRed = smdyn + 16384;    // [16 q][16 c (stride 17)][16 rp] = 34KB

    const int tid = threadIdx.x;
    const int cgB = blockIdx.x >> 1;       // colgroup 0..63
    const int rgB = blockIdx.x & 1;        // rowgroup 0..1
    const int cb  = cgB * 16;
    const int rb  = rgB * 32;

    // Load W column slice once (dup'd pairs)
    for (int i = tid; i < 16384; i += SCAN_THREADS) {
        int k = i >> 4, c = i & 15;
        float w = W[(size_t)k * HID + cb + c];
        wS2[i] = pack2(w, w);
    }
    __syncthreads();

    const int q    = tid >> 5;             // k-split 0..15 (warp id)
    const int l    = tid & 31;
    const int qd   = l & 3;                // row oct 0..3 -> rows qd*8..+8
    const int cgl  = l >> 2;               // col pair 0..7
    const int kbeg = q * 64;
    const int rowoff = rb + qd * 8;

    const int rrc = tid >> 4;              // reduce role: local col 0..15
    const int rrp = tid & 15;              // reduce role: row pair 0..15

    unsigned* cnt = &g_count;

    for (int t = 0; t < SEQL; ++t) {
        // ---- prefetch xi for epilogue (hidden under GEMM) ----
        float x0 = 0.f, x1 = 0.f;
        if (tid < 256) {
            const float* xit = xi + (size_t)t * BATCH * HID;
            x0 = __ldg(&xit[(size_t)(rb + 2 * rrp)     * HID + cb + rrc]);
            x1 = __ldg(&xit[(size_t)(rb + 2 * rrp + 1) * HID + cb + rrc]);
        }

        const float* hin = t ? hsT + (size_t)(t - 1) * BATCH * HID : h0T;
        const float* hp = hin + (size_t)kbeg * 64 + rowoff;
        const u64*   wp = wS2 + (size_t)kbeg * 16 + 2 * cgl;

        // acc[cc*4+ro]: col cc (0,1), row-pair ro (0..3) of the 8 rows
        u64 acc[8];
#pragma unroll
        for (int i = 0; i < 8; ++i) acc[i] = 0ull;

        // ping-pong pipeline: 16 chunks of 4 k, prefetch distance 1 chunk
        ulonglong2 Alo[4], Ahi[4], Blo[4], Bhi[4];
#pragma unroll
        for (int j = 0; j < 4; ++j) {
            Alo[j] = *(const ulonglong2*)(hp + (size_t)j * 64);
            Ahi[j] = *(const ulonglong2*)(hp + (size_t)j * 64 + 4);
        }

#pragma unroll 2
        for (int c4 = 0; c4 < 16; c4 += 2) {
            // load chunk c4+1 into B
#pragma unroll
            for (int j = 0; j < 4; ++j) {
                const float* p = hp + (size_t)((c4 + 1) * 4 + j) * 64;
                Blo[j] = *(const ulonglong2*)(p);
                Bhi[j] = *(const ulonglong2*)(p + 4);
            }
            // compute chunk c4 from A
#pragma unroll
            for (int j = 0; j < 4; ++j) {
                ulonglong2 wv = *(const ulonglong2*)(wp + (size_t)(c4 * 4 + j) * 16);
                acc[0] = fma2(Alo[j].x, wv.x, acc[0]);
                acc[1] = fma2(Alo[j].y, wv.x, acc[1]);
                acc[2] = fma2(Ahi[j].x, wv.x, acc[2]);
                acc[3] = fma2(Ahi[j].y, wv.x, acc[3]);
                acc[4] = fma2(Alo[j].x, wv.y, acc[4]);
                acc[5] = fma2(Alo[j].y, wv.y, acc[5]);
                acc[6] = fma2(Ahi[j].x, wv.y, acc[6]);
                acc[7] = fma2(Ahi[j].y, wv.y, acc[7]);
            }
            // load chunk c4+2 into A
            if (c4 + 2 < 16) {
#pragma unroll
                for (int j = 0; j < 4; ++j) {
                    const float* p = hp + (size_t)((c4 + 2) * 4 + j) * 64;
                    Alo[j] = *(const ulonglong2*)(p);
                    Ahi[j] = *(const ulonglong2*)(p + 4);
                }
            }
            // compute chunk c4+1 from B
#pragma unroll
            for (int j = 0; j < 4; ++j) {
                ulonglong2 wv = *(const ulonglong2*)(wp + (size_t)((c4 + 1) * 4 + j) * 16);
                acc[0] = fma2(Blo[j].x, wv.x, acc[0]);
                acc[1] = fma2(Blo[j].y, wv.x, acc[1]);
                acc[2] = fma2(Bhi[j].x, wv.x, acc[2]);
                acc[3] = fma2(Bhi[j].y, wv.x, acc[3]);
                acc[4] = fma2(Blo[j].x, wv.y, acc[4]);
                acc[5] = fma2(Blo[j].y, wv.y, acc[5]);
                acc[6] = fma2(Bhi[j].x, wv.y, acc[6]);
                acc[7] = fma2(Bhi[j].y, wv.y, acc[7]);
            }
        }

        // ---- partial store: sRed[q][c][rp], c stride 17 to dodge conflicts
        {
            u64* base = sRed + (size_t)q * 272;   // 16*17
#pragma unroll
            for (int cc = 0; cc < 2; ++cc)
#pragma unroll
                for (int ro = 0; ro < 4; ++ro)
                    base[(size_t)(2 * cgl + cc) * 17 + (qd * 4 + ro)] = acc[cc * 4 + ro];
        }
        __syncthreads();

        // ---- 16-way reduce + tanh + store h_t ----
        if (tid < 256) {
            u64 s = sRed[(size_t)rrc * 17 + rrp];
#pragma unroll
            for (int qq = 1; qq < 16; ++qq)
                s = add2(s, sRed[(size_t)qq * 272 + (size_t)rrc * 17 + rrp]);
            float2 f = unpack2(s);
            float v0 = tanhf(f.x + x0);
            float v1 = tanhf(f.y + x1);
            *(u64*)(hsT + (size_t)t * BATCH * HID + (size_t)(cb + rrc) * 64 + rb + 2 * rrp)
                = pack2(v0, v1);
        }

        // ---- grid barrier: release-increment + poll monotonic counter ----
        __syncthreads();
        if (tid == 0) {
            asm volatile("red.release.gpu.global.add.u32 [%0], 1;"
                         :: "l"(cnt) : "memory");
        }
        if (tid < 32) {
            const unsigned target = (unsigned)NBLK * (unsigned)(t + 1);
            unsigned cur;
            do {
                asm volatile("ld.acquire.gpu.u32 %0,[%1];"
                             : "=r"(cur) : "l"(cnt) : "memory");
            } while (cur < target);
        }
        __syncthreads();
    }
}

// ---------------------------------------------------------------------------
// Double-buffered 128x128x16 f32x2 GEMM: C = A @ B + bias, optional leaky.
// ATRANS: A stored as [M/64][K][64] (transposed hidden-state history).
// ---------------------------------------------------------------------------
template <bool ATRANS, bool LEAKY>
__global__ __launch_bounds__(256) void sgemm_db(
    const float* __restrict__ A, const float* __restrict__ B,
    const float* __restrict__ bias, float* __restrict__ C,
    int M, int N, int K)
{
    constexpr int BM = 128, BN = 128, BK = 16;
    __shared__ __align__(16) float As[2][BK][BM];
    __shared__ __align__(16) float Bs[2][BK][BN];

    const int tid = threadIdx.x;
    const int bx = blockIdx.x, by = blockIdx.y;
    const int tx = tid & 15, ty = tid >> 4;

    u64 acc[8][4];
#pragma unroll
    for (int i = 0; i < 8; i++)
#pragma unroll
        for (int j = 0; j < 4; j++) acc[i][j] = 0ull;

    const int aRow = tid >> 1, aC = (tid & 1) * 8;
    const int at_t = tid >> 7, at_kk = (tid >> 3) & 15, at_b = (tid & 7) * 8;
    const int bRow = tid >> 4, bCol = (tid & 15) * 8;

    float4 A0, A1, B0, B1;

    auto loadT = [&](int k0) {
        if (!ATRANS) {
            const float* p = A + (size_t)(by * BM + aRow) * K + k0 + aC;
            A0 = *(const float4*)(p);
            A1 = *(const float4*)(p + 4);
        } else {
            const float* p = A + ((size_t)(by * 2 + at_t) * K + (k0 + at_kk)) * 64 + at_b;
            A0 = *(const float4*)(p);
            A1 = *(const float4*)(p + 4);
        }
        const float* pb = B + (size_t)(k0 + bRow) * N + bx * BN + bCol;
        B0 = *(const float4*)(pb);
        B1 = *(const float4*)(pb + 4);
    };
    auto storeT = [&](int buf) {
        if (!ATRANS) {
            As[buf][aC + 0][aRow] = A0.x; As[buf][aC + 1][aRow] = A0.y;
            As[buf][aC + 2][aRow] = A0.z; As[buf][aC + 3][aRow] = A0.w;
            As[buf][aC + 4][aRow] = A1.x; As[buf][aC + 5][aRow] = A1.y;
            As[buf][aC + 6][aRow] = A1.z; As[buf][aC + 7][aRow] = A1.w;
        } else {
            *(float4*)&As[buf][at_kk][at_t * 64 + at_b]     = A0;
            *(float4*)&As[buf][at_kk][at_t * 64 + at_b + 4] = A1;
        }
        *(float4*)&Bs[buf][bRow][bCol]     = B0;
        *(float4*)&Bs[buf][bRow][bCol + 4] = B1;
    };

    loadT(0);
    storeT(0);
    __syncthreads();

    const int nIter = K / BK;
    for (int it = 0; it < nIter; ++it) {
        const int cur = it & 1;
        if (it + 1 < nIter) loadT((it + 1) * BK);

#pragma unroll
        for (int kk = 0; kk < BK; kk++) {
            float4 alo = *(const float4*)&As[cur][kk][ty * 8];
            float4 ahi = *(const float4*)&As[cur][kk][ty * 8 + 4];
            ulonglong2 b01 = *(const ulonglong2*)&Bs[cur][kk][tx * 8];
            ulonglong2 b23 = *(const ulonglong2*)&Bs[cur][kk][tx * 8 + 4];
            float a[8] = {alo.x, alo.y, alo.z, alo.w, ahi.x, ahi.y, ahi.z, ahi.w};
#pragma unroll
            for (int i = 0; i < 8; i++) {
                u64 ad = pack2(a[i], a[i]);
                acc[i][0] = fma2(ad, b01.x, acc[i][0]);
                acc[i][1] = fma2(ad, b01.y, acc[i][1]);
                acc[i][2] = fma2(ad, b23.x, acc[i][2]);
                acc[i][3] = fma2(ad, b23.y, acc[i][3]);
            }
        }
        if (it + 1 < nIter) storeT(cur ^ 1);
        __syncthreads();
    }

    const int row0 = by * BM + ty * 8, col0 = bx * BN + tx * 8;
#pragma unroll
    for (int i = 0; i < 8; i++) {
        float out[8];
#pragma unroll
        for (int j = 0; j < 4; j++) {
            float2 f = unpack2(acc[i][j]);
            out[2 * j] = f.x; out[2 * j + 1] = f.y;
        }
#pragma unroll
        for (int j = 0; j < 8; j++) {
            float v = out[j] + bias[col0 + j];
            if (LEAKY) v = v >= 0.f ? v : 0.01f * v;
            out[j] = v;
        }
        *(float4*)&C[(size_t)(row0 + i) * N + col0]     = make_float4(out[0], out[1], out[2], out[3]);
        *(float4*)&C[(size_t)(row0 + i) * N + col0 + 4] = make_float4(out[4], out[5], out[6], out[7]);
    }
}

// ---------------------------------------------------------------------------
__global__ void transpose_h0(const float* __restrict__ in, float* __restrict__ out) {
    int i = blockIdx.x * 256 + threadIdx.x;        // 65536
    int c = i >> 6, r = i & 63;
    out[i] = in[(size_t)r * HID + c];              // out[c][r]
}
// Also resets the scan barrier counter for the next launch (stream-ordered).
__global__ void transpose_hfinal(const float* __restrict__ hsTlast, float* __restrict__ out) {
    int i = blockIdx.x * 256 + threadIdx.x;        // 65536
    int r = i >> 10, c = i & 1023;
    out[i] = hsTlast[(size_t)c * 64 + r];          // out[r][c]
    if (i == 0) g_count = 0;
}

// ---------------------------------------------------------------------------
extern "C" void kernel_launch(void* const* d_in, const int* in_sizes, int n_in,
                              void* d_out, int out_size)
{
    const float* x   = (const float*)d_in[0];
    const float* h0  = (const float*)d_in[1];
    const float* i_h = (const float*)d_in[2];
    const float* h_h = (const float*)d_in[3];
    const float* h_o = (const float*)d_in[4];
    const float* b_i = (const float*)d_in[5];
    const float* b_o = (const float*)d_in[6];
    float* out = (float*)d_out;

    float *xi = nullptr, *hsT = nullptr, *h0T = nullptr;
    cudaGetSymbolAddress((void**)&xi,  g_xi);
    cudaGetSymbolAddress((void**)&hsT, g_hsT);
    cudaGetSymbolAddress((void**)&h0T, g_h0T);

    const int SCAN_SMEM = (16384 + 16 * 272) * 8;   // 131072 + 34816 = 165888
    static int smem_set = 0;
    if (!smem_set) {
        cudaFuncSetAttribute(rnn_scan, cudaFuncAttributeMaxDynamicSharedMemorySize, SCAN_SMEM);
        smem_set = 1;
    }

    // 0) transpose h0 -> [c][r]
    transpose_h0<<<256, 256>>>(h0, h0T);

    // 1) xi = x @ i_h + b_i : [32768,512]@[512,1024]
    {
        dim3 grid(HID / 128, (SEQL * BATCH) / 128);
        sgemm_db<false, false><<<grid, 256>>>(x, i_h, b_i, xi, SEQL * BATCH, HID, INF);
    }

    // 2) persistent scan (all 512 steps in one launch)
    rnn_scan<<<NBLK, SCAN_THREADS, SCAN_SMEM>>>(h0T, h_h, xi, hsT);

    // 3) outputs = leaky_relu(hsT @ h_o + b_o) : [32768,1024]@[1024,512]
    {
        dim3 grid(OUTF / 128, (SEQL * BATCH) / 128);
        sgemm_db<true, true><<<grid, 256>>>(hsT, h_o, b_o, out, SEQL * BATCH, OUTF, HID);
    }

    // 4) h_final = transpose(hsT[511])  (+ barrier counter reset)
    transpose_hfinal<<<256, 256>>>(hsT + (size_t)(SEQL - 1) * BATCH * HID,
                                   out + (size_t)SEQL * BATCH * OUTF);
}

// round 8
// speedup vs baseline: 1.4356x; 1.0336x over previous
#include <cuda_runtime.h>
#include <math.h>

#define SEQL 512
#define BATCH 64
#define INF 512
#define HID 1024
#define OUTF 512
#define NBLK 128
#define SCAN_THREADS 512

typedef unsigned long long u64;

// Scratch (device globals; allocation-free)
__device__ float g_xi [(size_t)SEQL * BATCH * HID];   // [t][b][c] row-major
__device__ float g_hsT[(size_t)SEQL * BATCH * HID];   // [t][c][r] transposed
__device__ float g_h0T[(size_t)BATCH * HID];          // [c][r]
__device__ unsigned g_count = 0;                      // monotonic barrier counter

// ---------------- f32x2 helpers ----------------
__device__ __forceinline__ u64 pack2(float x, float y) {
    u64 d; asm("mov.b64 %0,{%1,%2};" : "=l"(d) : "f"(x), "f"(y)); return d;
}
__device__ __forceinline__ float2 unpack2(u64 d) {
    float2 v; asm("mov.b64 {%0,%1},%2;" : "=f"(v.x), "=f"(v.y) : "l"(d)); return v;
}
__device__ __forceinline__ u64 fma2(u64 a, u64 b, u64 c) {
    u64 d; asm("fma.rn.f32x2 %0,%1,%2,%3;" : "=l"(d) : "l"(a), "l"(b), "l"(c)); return d;
}
__device__ __forceinline__ u64 add2(u64 a, u64 b) {
    u64 d; asm("add.rn.f32x2 %0,%1,%2;" : "=l"(d) : "l"(a), "l"(b)); return d;
}

// ---------------------------------------------------------------------------
// Persistent scan: h_t = tanh(xi_t + h_{t-1} @ W).
// 128 blocks = 32 colgroups(32 cols) x 4 rowgroups(16 rows); 512 threads.
// Block reads only its 16 rows of h (64KB/step -> 8MB/step chip-wide).
// W slice [1024][32] in SMEM as plain float2 (128KB); (w,w) pairs built with
// MOVs at use. 16 warps = 16 k-splits (64 k each); lane tile 8 rows x 2 cols.
// sRed [16 q][32 c][8 rp pad 9]; 256-thread reduce; leaderless barrier.
// ---------------------------------------------------------------------------
__global__ void __launch_bounds__(SCAN_THREADS, 1) rnn_scan(
    const float* __restrict__ h0T, const float* __restrict__ W,
    const float* __restrict__ xi, float* __restrict__ hsT)
{
    extern __shared__ char smdyn[];
    float2* wS = (float2*)smdyn;                 // [1024][16] float2 = 128KB
    u64*  sRed = (u64*)(smdyn + 131072);         // [16][32][9] u64 = 36864B

    const int tid = threadIdx.x;
    const int cgB = blockIdx.x >> 2;       // colgroup 0..31
    const int rgB = blockIdx.x & 3;        // rowgroup 0..3
    const int cb  = cgB * 32;
    const int rb  = rgB * 16;

    // Load W column slice once: wS[k][c2] = (W[k][cb+2c2], W[k][cb+2c2+1])
    for (int i = tid; i < 1024 * 16; i += SCAN_THREADS) {
        int k = i >> 4, c2 = i & 15;
        wS[i] = make_float2(W[(size_t)k * HID + cb + 2 * c2],
                            W[(size_t)k * HID + cb + 2 * c2 + 1]);
    }
    __syncthreads();

    const int q    = tid >> 5;             // k-split 0..15 (warp id)
    const int l    = tid & 31;
    const int qd   = l & 1;                // row half: rows qd*8..+8 of 16
    const int cgl  = l >> 1;               // col pair 0..15
    const int kbeg = q * 64;
    const int rowoff = rb + qd * 8;

    const int rrc = tid >> 3;              // reduce: local col 0..31
    const int rrp = tid & 7;               // reduce: row pair 0..7

    unsigned* cnt = &g_count;

    for (int t = 0; t < SEQL; ++t) {
        // ---- prefetch xi for epilogue (hidden under GEMM) ----
        float x0 = 0.f, x1 = 0.f;
        if (tid < 256) {
            const float* xit = xi + (size_t)t * BATCH * HID;
            x0 = __ldg(&xit[(size_t)(rb + 2 * rrp)     * HID + cb + rrc]);
            x1 = __ldg(&xit[(size_t)(rb + 2 * rrp + 1) * HID + cb + rrc]);
        }

        const float* hin = t ? hsT + (size_t)(t - 1) * BATCH * HID : h0T;
        const float* hp = hin + (size_t)kbeg * 64 + rowoff;
        const float2* wp = wS + (size_t)kbeg * 16 + cgl;

        // acc[cc*4+ro]: col cc (0,1), row-pair ro (0..3) of the 8 rows
        u64 acc[8];
#pragma unroll
        for (int i = 0; i < 8; ++i) acc[i] = 0ull;

        // ping-pong pipeline: 16 chunks of 4 k, prefetch distance 1 chunk
        ulonglong2 Alo[4], Ahi[4], Blo[4], Bhi[4];
#pragma unroll
        for (int j = 0; j < 4; ++j) {
            Alo[j] = *(const ulonglong2*)(hp + (size_t)j * 64);
            Ahi[j] = *(const ulonglong2*)(hp + (size_t)j * 64 + 4);
        }

#pragma unroll 2
        for (int c4 = 0; c4 < 16; c4 += 2) {
            // load chunk c4+1 into B
#pragma unroll
            for (int j = 0; j < 4; ++j) {
                const float* p = hp + (size_t)((c4 + 1) * 4 + j) * 64;
                Blo[j] = *(const ulonglong2*)(p);
                Bhi[j] = *(const ulonglong2*)(p + 4);
            }
            // compute chunk c4 from A
#pragma unroll
            for (int j = 0; j < 4; ++j) {
                float2 w2 = wp[(size_t)(c4 * 4 + j) * 16];
                u64 wx = pack2(w2.x, w2.x);
                u64 wy = pack2(w2.y, w2.y);
                acc[0] = fma2(Alo[j].x, wx, acc[0]);
                acc[1] = fma2(Alo[j].y, wx, acc[1]);
                acc[2] = fma2(Ahi[j].x, wx, acc[2]);
                acc[3] = fma2(Ahi[j].y, wx, acc[3]);
                acc[4] = fma2(Alo[j].x, wy, acc[4]);
                acc[5] = fma2(Alo[j].y, wy, acc[5]);
                acc[6] = fma2(Ahi[j].x, wy, acc[6]);
                acc[7] = fma2(Ahi[j].y, wy, acc[7]);
            }
            // load chunk c4+2 into A
            if (c4 + 2 < 16) {
#pragma unroll
                for (int j = 0; j < 4; ++j) {
                    const float* p = hp + (size_t)((c4 + 2) * 4 + j) * 64;
                    Alo[j] = *(const ulonglong2*)(p);
                    Ahi[j] = *(const ulonglong2*)(p + 4);
                }
            }
            // compute chunk c4+1 from B
#pragma unroll
            for (int j = 0; j < 4; ++j) {
                float2 w2 = wp[(size_t)((c4 + 1) * 4 + j) * 16];
                u64 wx = pack2(w2.x, w2.x);
                u64 wy = pack2(w2.y, w2.y);
                acc[0] = fma2(Blo[j].x, wx, acc[0]);
                acc[1] = fma2(Blo[j].y, wx, acc[1]);
                acc[2] = fma2(Bhi[j].x, wx, acc[2]);
                acc[3] = fma2(Bhi[j].y, wx, acc[3]);
                acc[4] = fma2(Blo[j].x, wy, acc[4]);
                acc[5] = fma2(Blo[j].y, wy, acc[5]);
                acc[6] = fma2(Bhi[j].x, wy, acc[6]);
                acc[7] = fma2(Bhi[j].y, wy, acc[7]);
            }
        }

        // ---- partial store: sRed[q][2cgl+cc][qd*4+ro] (rp padded to 9) ----
        {
            u64* base = sRed + (size_t)q * 288;   // 32*9
#pragma unroll
            for (int cc = 0; cc < 2; ++cc)
#pragma unroll
                for (int ro = 0; ro < 4; ++ro)
                    base[(size_t)(2 * cgl + cc) * 9 + (qd * 4 + ro)] = acc[cc * 4 + ro];
        }
        __syncthreads();

        // ---- 16-way reduce + tanh + store h_t (256 threads, 1 u64 each) ----
        if (tid < 256) {
            u64 s = sRed[(size_t)rrc * 9 + rrp];
#pragma unroll
            for (int qq = 1; qq < 16; ++qq)
                s = add2(s, sRed[(size_t)qq * 288 + (size_t)rrc * 9 + rrp]);
            float2 f = unpack2(s);
            float v0 = tanhf(f.x + x0);
            float v1 = tanhf(f.y + x1);
            *(u64*)(hsT + (size_t)t * BATCH * HID + (size_t)(cb + rrc) * 64 + rb + 2 * rrp)
                = pack2(v0, v1);
        }

        // ---- grid barrier: release-increment + poll monotonic counter ----
        __syncthreads();
        if (tid == 0) {
            asm volatile("red.release.gpu.global.add.u32 [%0], 1;"
                         :: "l"(cnt) : "memory");
        }
        if (tid < 32) {
            const unsigned target = (unsigned)NBLK * (unsigned)(t + 1);
            unsigned cur;
            do {
                asm volatile("ld.acquire.gpu.u32 %0,[%1];"
                             : "=r"(cur) : "l"(cnt) : "memory");
            } while (cur < target);
        }
        __syncthreads();
    }
}

// ---------------------------------------------------------------------------
// Double-buffered 128x128x16 f32x2 GEMM: C = A @ B + bias, optional leaky.
// ATRANS: A stored as [M/64][K][64] (transposed hidden-state history).
// ---------------------------------------------------------------------------
template <bool ATRANS, bool LEAKY>
__global__ __launch_bounds__(256) void sgemm_db(
    const float* __restrict__ A, const float* __restrict__ B,
    const float* __restrict__ bias, float* __restrict__ C,
    int M, int N, int K)
{
    constexpr int BM = 128, BN = 128, BK = 16;
    __shared__ __align__(16) float As[2][BK][BM];
    __shared__ __align__(16) float Bs[2][BK][BN];

    const int tid = threadIdx.x;
    const int bx = blockIdx.x, by = blockIdx.y;
    const int tx = tid & 15, ty = tid >> 4;

    u64 acc[8][4];
#pragma unroll
    for (int i = 0; i < 8; i++)
#pragma unroll
        for (int j = 0; j < 4; j++) acc[i][j] = 0ull;

    const int aRow = tid >> 1, aC = (tid & 1) * 8;
    const int at_t = tid >> 7, at_kk = (tid >> 3) & 15, at_b = (tid & 7) * 8;
    const int bRow = tid >> 4, bCol = (tid & 15) * 8;

    float4 A0, A1, B0, B1;

    auto loadT = [&](int k0) {
        if (!ATRANS) {
            const float* p = A + (size_t)(by * BM + aRow) * K + k0 + aC;
            A0 = *(const float4*)(p);
            A1 = *(const float4*)(p + 4);
        } else {
            const float* p = A + ((size_t)(by * 2 + at_t) * K + (k0 + at_kk)) * 64 + at_b;
            A0 = *(const float4*)(p);
            A1 = *(const float4*)(p + 4);
        }
        const float* pb = B + (size_t)(k0 + bRow) * N + bx * BN + bCol;
        B0 = *(const float4*)(pb);
        B1 = *(const float4*)(pb + 4);
    };
    auto storeT = [&](int buf) {
        if (!ATRANS) {
            As[buf][aC + 0][aRow] = A0.x; As[buf][aC + 1][aRow] = A0.y;
            As[buf][aC + 2][aRow] = A0.z; As[buf][aC + 3][aRow] = A0.w;
            As[buf][aC + 4][aRow] = A1.x; As[buf][aC + 5][aRow] = A1.y;
            As[buf][aC + 6][aRow] = A1.z; As[buf][aC + 7][aRow] = A1.w;
        } else {
            *(float4*)&As[buf][at_kk][at_t * 64 + at_b]     = A0;
            *(float4*)&As[buf][at_kk][at_t * 64 + at_b + 4] = A1;
        }
        *(float4*)&Bs[buf][bRow][bCol]     = B0;
        *(float4*)&Bs[buf][bRow][bCol + 4] = B1;
    };

    loadT(0);
    storeT(0);
    __syncthreads();

    const int nIter = K / BK;
    for (int it = 0; it < nIter; ++it) {
        const int cur = it & 1;
        if (it + 1 < nIter) loadT((it + 1) * BK);

#pragma unroll
        for (int kk = 0; kk < BK; kk++) {
            float4 alo = *(const float4*)&As[cur][kk][ty * 8];
            float4 ahi = *(const float4*)&As[cur][kk][ty * 8 + 4];
            ulonglong2 b01 = *(const ulonglong2*)&Bs[cur][kk][tx * 8];
            ulonglong2 b23 = *(const ulonglong2*)&Bs[cur][kk][tx * 8 + 4];
            float a[8] = {alo.x, alo.y, alo.z, alo.w, ahi.x, ahi.y, ahi.z, ahi.w};
#pragma unroll
            for (int i = 0; i < 8; i++) {
                u64 ad = pack2(a[i], a[i]);
                acc[i][0] = fma2(ad, b01.x, acc[i][0]);
                acc[i][1] = fma2(ad, b01.y, acc[i][1]);
                acc[i][2] = fma2(ad, b23.x, acc[i][2]);
                acc[i][3] = fma2(ad, b23.y, acc[i][3]);
            }
        }
        if (it + 1 < nIter) storeT(cur ^ 1);
        __syncthreads();
    }

    const int row0 = by * BM + ty * 8, col0 = bx * BN + tx * 8;
#pragma unroll
    for (int i = 0; i < 8; i++) {
        float out[8];
#pragma unroll
        for (int j = 0; j < 4; j++) {
            float2 f = unpack2(acc[i][j]);
            out[2 * j] = f.x; out[2 * j + 1] = f.y;
        }
#pragma unroll
        for (int j = 0; j < 8; j++) {
            float v = out[j] + bias[col0 + j];
            if (LEAKY) v = v >= 0.f ? v : 0.01f * v;
            out[j] = v;
        }
        *(float4*)&C[(size_t)(row0 + i) * N + col0]     = make_float4(out[0], out[1], out[2], out[3]);
        *(float4*)&C[(size_t)(row0 + i) * N + col0 + 4] = make_float4(out[4], out[5], out[6], out[7]);
    }
}

// ---------------------------------------------------------------------------
__global__ void transpose_h0(const float* __restrict__ in, float* __restrict__ out) {
    int i = blockIdx.x * 256 + threadIdx.x;        // 65536
    int c = i >> 6, r = i & 63;
    out[i] = in[(size_t)r * HID + c];              // out[c][r]
}
// Also resets the scan barrier counter for the next launch (stream-ordered).
__global__ void transpose_hfinal(const float* __restrict__ hsTlast, float* __restrict__ out) {
    int i = blockIdx.x * 256 + threadIdx.x;        // 65536
    int r = i >> 10, c = i & 1023;
    out[i] = hsTlast[(size_t)c * 64 + r];          // out[r][c]
    if (i == 0) g_count = 0;
}

// ---------------------------------------------------------------------------
extern "C" void kernel_launch(void* const* d_in, const int* in_sizes, int n_in,
                              void* d_out, int out_size)
{
    const float* x   = (const float*)d_in[0];
    const float* h0  = (const float*)d_in[1];
    const float* i_h = (const float*)d_in[2];
    const float* h_h = (const float*)d_in[3];
    const float* h_o = (const float*)d_in[4];
    const float* b_i = (const float*)d_in[5];
    const float* b_o = (const float*)d_in[6];
    float* out = (float*)d_out;

    float *xi = nullptr, *hsT = nullptr, *h0T = nullptr;
    cudaGetSymbolAddress((void**)&xi,  g_xi);
    cudaGetSymbolAddress((void**)&hsT, g_hsT);
    cudaGetSymbolAddress((void**)&h0T, g_h0T);

    const int SCAN_SMEM = 131072 + 16 * 288 * 8;   // 131072 + 36864 = 167936
    static int smem_set = 0;
    if (!smem_set) {
        cudaFuncSetAttribute(rnn_scan, cudaFuncAttributeMaxDynamicSharedMemorySize, SCAN_SMEM);
        smem_set = 1;
    }

    // 0) transpose h0 -> [c][r]
    transpose_h0<<<256, 256>>>(h0, h0T);

    // 1) xi = x @ i_h + b_i : [32768,512]@[512,1024]
    {
        dim3 grid(HID / 128, (SEQL * BATCH) / 128);
        sgemm_db<false, false><<<grid, 256>>>(x, i_h, b_i, xi, SEQL * BATCH, HID, INF);
    }

    // 2) persistent scan (all 512 steps in one launch)
    rnn_scan<<<NBLK, SCAN_THREADS, SCAN_SMEM>>>(h0T, h_h, xi, hsT);

    // 3) outputs = leaky_relu(hsT @ h_o + b_o) : [32768,1024]@[1024,512]
    {
        dim3 grid(OUTF / 128, (SEQL * BATCH) / 128);
        sgemm_db<true, true><<<grid, 256>>>(hsT, h_o, b_o, out, SEQL * BATCH, OUTF, HID);
    }

    // 4) h_final = transpose(hsT[511])  (+ barrier counter reset)
    transpose_hfinal<<<256, 256>>>(hsT + (size_t)(SEQL - 1) * BATCH * HID,
                                   out + (size_t)SEQL * BATCH * OUTF);
}